// round 4
// baseline (speedup 1.0000x reference)
#include <cuda_runtime.h>
#include <cuda_fp16.h>
#include <cstdint>

#define NN 50000
#define EE 800000
#define CC 512     // H*HID
#define HH 8
#define FF 64

// ---------------- scratch (device globals; no allocation allowed) ----------
__device__ __half g_feat[(size_t)NN * CC];  // 51.2 MB projected features (fp16)
__device__ float g_el[NN * HH];
__device__ float g_er[NN * HH];
__device__ float g_h[NN * FF];              // layer activations (fp32)
__device__ int   g_rowptr[NN + 1];
__device__ int   g_cnt[NN];
__device__ int   g_fill[NN];
__device__ int   g_col[EE];                 // src ids grouped by dst

// ---------------- CSR build ------------------------------------------------
__global__ void k_zero() {
    int i = blockIdx.x * blockDim.x + threadIdx.x;
    if (i < NN) { g_cnt[i] = 0; g_fill[i] = 0; }
}

__global__ void k_hist(const int* __restrict__ dst) {
    int e = blockIdx.x * blockDim.x + threadIdx.x;
    if (e < EE) atomicAdd(&g_cnt[dst[e]], 1);
}

__global__ void k_scan() {
    __shared__ int sh[1024];
    __shared__ int s_off;
    int tid = threadIdx.x;
    if (tid == 0) s_off = 0;
    __syncthreads();
    for (int base = 0; base < NN; base += 1024) {
        int idx = base + tid;
        int orig = (idx < NN) ? g_cnt[idx] : 0;
        int v = orig;
        sh[tid] = v;
        __syncthreads();
        for (int off = 1; off < 1024; off <<= 1) {
            int add = (tid >= off) ? sh[tid - off] : 0;
            __syncthreads();
            v += add; sh[tid] = v;
            __syncthreads();
        }
        int myoff = s_off;
        if (idx < NN) g_rowptr[idx] = myoff + (v - orig);
        __syncthreads();
        if (tid == 1023) s_off = myoff + v;
        __syncthreads();
    }
    if (tid == 0) g_rowptr[NN] = s_off;
}

__global__ void k_scatter(const int* __restrict__ src, const int* __restrict__ dst) {
    int e = blockIdx.x * blockDim.x + threadIdx.x;
    if (e < EE) {
        int d = dst[e];
        int pos = g_rowptr[d] + atomicAdd(&g_fill[d], 1);
        g_col[pos] = src[e];
    }
}

// ---------------- tf32 tensor-core GEMM ------------------------------------
// C[M,NCol] = A[M,K] @ B[NCol,K]^T (+bias).  K multiple of 32, NCol mult of 64.
__device__ __forceinline__ uint32_t f2tf(float f) {
    uint32_t r;
    asm("cvt.rna.tf32.f32 %0, %1;" : "=r"(r) : "f"(f));
    return r;
}

__device__ __forceinline__ void store_c(float* C, size_t idx, float v) { C[idx] = v; }
__device__ __forceinline__ void store_c(__half* C, size_t idx, float v) { C[idx] = __float2half_rn(v); }

template <typename OutT>
__global__ __launch_bounds__(256, 2) void k_gemm_tc(
    const float* __restrict__ A, const float* __restrict__ B,
    const float* __restrict__ bias, OutT* __restrict__ C,
    int M, int NCol, int K)
{
    // fragment-layout smem: [kstep(4)][tile(8)][lane(32)][quad]
    __shared__ uint32_t As2[4 * 8 * 32 * 4];   // 16 KB
    __shared__ uint32_t Bs2[4 * 8 * 32 * 2];   //  8 KB
    const int tid = threadIdx.x;
    const int lane = tid & 31, wid = tid >> 5;
    const int wm = wid & 3, wn = wid >> 2;          // warp grid 4(M) x 2(N)
    const int m0 = blockIdx.y * 128, n0 = blockIdx.x * 64;

    float acc[2][4][4];
#pragma unroll
    for (int im = 0; im < 2; im++)
#pragma unroll
        for (int in = 0; in < 4; in++)
#pragma unroll
            for (int q = 0; q < 4; q++) acc[im][in][q] = 0.f;

    float4 rA[4], rB[2];

    // prefetch slab 0
#pragma unroll
    for (int i = 0; i < 4; i++) {
        int idx = tid + 256 * i;
        int row = idx >> 3, c0 = (idx & 7) << 2;
        int gr = m0 + row;
        rA[i] = (gr < M) ? *(const float4*)(A + (size_t)gr * K + c0)
                         : make_float4(0.f, 0.f, 0.f, 0.f);
    }
#pragma unroll
    for (int i = 0; i < 2; i++) {
        int idx = tid + 256 * i;
        int row = idx >> 3, c0 = (idx & 7) << 2;
        rB[i] = *(const float4*)(B + (size_t)(n0 + row) * K + c0);
    }

    for (int kt = 0; kt < K; kt += 32) {
        __syncthreads();
        // ---- store A fragments (pre-permuted, tf32-converted) ----
#pragma unroll
        for (int i = 0; i < 4; i++) {
            int idx = tid + 256 * i;
            int row = idx >> 3, c0 = (idx & 7) << 2;
            int mt = row >> 4, rr = row & 15;
            int q1 = rr >> 3, lrow = rr & 7;
            int ks = c0 >> 3, q0 = (c0 >> 2) & 1;
            int quad = q1 * 2 + q0;
            int base = (ks * 8 + mt) * 32;
            int lb = lrow * 4 + ks * 8;
            As2[(base + ((lb + 0) & 31)) * 4 + quad] = f2tf(rA[i].x);
            As2[(base + ((lb + 1) & 31)) * 4 + quad] = f2tf(rA[i].y);
            As2[(base + ((lb + 2) & 31)) * 4 + quad] = f2tf(rA[i].z);
            As2[(base + ((lb + 3) & 31)) * 4 + quad] = f2tf(rA[i].w);
        }
        // ---- store B fragments ----
#pragma unroll
        for (int i = 0; i < 2; i++) {
            int idx = tid + 256 * i;
            int row = idx >> 3, c0 = (idx & 7) << 2;
            int nt = row >> 3, ln = row & 7;
            int ks = c0 >> 3, q0 = (c0 >> 2) & 1;
            int base = (ks * 8 + nt) * 32;
            int lb = ln * 4 + ks * 8;
            Bs2[(base + ((lb + 0) & 31)) * 2 + q0] = f2tf(rB[i].x);
            Bs2[(base + ((lb + 1) & 31)) * 2 + q0] = f2tf(rB[i].y);
            Bs2[(base + ((lb + 2) & 31)) * 2 + q0] = f2tf(rB[i].z);
            Bs2[(base + ((lb + 3) & 31)) * 2 + q0] = f2tf(rB[i].w);
        }
        __syncthreads();

        // ---- prefetch next slab (overlaps with mma below) ----
        if (kt + 32 < K) {
#pragma unroll
            for (int i = 0; i < 4; i++) {
                int idx = tid + 256 * i;
                int row = idx >> 3, c0 = (idx & 7) << 2;
                int gr = m0 + row;
                rA[i] = (gr < M) ? *(const float4*)(A + (size_t)gr * K + kt + 32 + c0)
                                 : make_float4(0.f, 0.f, 0.f, 0.f);
            }
#pragma unroll
            for (int i = 0; i < 2; i++) {
                int idx = tid + 256 * i;
                int row = idx >> 3, c0 = (idx & 7) << 2;
                rB[i] = *(const float4*)(B + (size_t)(n0 + row) * K + kt + 32 + c0);
            }
        }

        // ---- compute: 4 k-steps x 8 mma per warp ----
#pragma unroll
        for (int ks = 0; ks < 4; ks++) {
            int ll = (lane + ks * 8) & 31;
            uint32_t a[2][4];
#pragma unroll
            for (int im = 0; im < 2; im++) {
                uint4 v = *(const uint4*)(As2 + ((ks * 8 + wm * 2 + im) * 32 + ll) * 4);
                a[im][0] = v.x; a[im][2] = v.y; a[im][1] = v.z; a[im][3] = v.w;
            }
            uint32_t b[4][2];
#pragma unroll
            for (int in = 0; in < 4; in++) {
                uint2 v = *(const uint2*)(Bs2 + ((ks * 8 + wn * 4 + in) * 32 + ll) * 2);
                b[in][0] = v.x; b[in][1] = v.y;
            }
#pragma unroll
            for (int im = 0; im < 2; im++)
#pragma unroll
                for (int in = 0; in < 4; in++)
                    asm volatile(
                        "mma.sync.aligned.m16n8k8.row.col.f32.tf32.tf32.f32 "
                        "{%0,%1,%2,%3},{%4,%5,%6,%7},{%8,%9},{%0,%1,%2,%3};"
                        : "+f"(acc[im][in][0]), "+f"(acc[im][in][1]),
                          "+f"(acc[im][in][2]), "+f"(acc[im][in][3])
                        : "r"(a[im][0]), "r"(a[im][1]), "r"(a[im][2]), "r"(a[im][3]),
                          "r"(b[in][0]), "r"(b[in][1]));
        }
    }

    // ---- epilogue ----
    int gid = lane >> 2, tig = lane & 3;
#pragma unroll
    for (int im = 0; im < 2; im++) {
        int r = m0 + wm * 32 + im * 16 + gid;
#pragma unroll
        for (int in = 0; in < 4; in++) {
            int c = n0 + wn * 32 + in * 8 + tig * 2;
            float b0v = bias ? bias[c] : 0.f;
            float b1v = bias ? bias[c + 1] : 0.f;
            if (r < M) {
                store_c(C, (size_t)r * NCol + c,     acc[im][in][0] + b0v);
                store_c(C, (size_t)r * NCol + c + 1, acc[im][in][1] + b1v);
            }
            if (r + 8 < M) {
                store_c(C, (size_t)(r + 8) * NCol + c,     acc[im][in][2] + b0v);
                store_c(C, (size_t)(r + 8) * NCol + c + 1, acc[im][in][3] + b1v);
            }
        }
    }
}

// ---------------- el/er: per-(node,head) dot of feat with al/ar ------------
__global__ void k_eler(const float* __restrict__ al, const float* __restrict__ ar) {
    int n = blockIdx.x;
    int w = threadIdx.x >> 5, lane = threadIdx.x & 31;
    const __half2* f = (const __half2*)g_feat + (size_t)n * (CC / 2) + w * (FF / 2);
    float2 v = __half22float2(f[lane]);
    float a0 = al[w * FF + lane * 2], a1 = al[w * FF + lane * 2 + 1];
    float r0 = ar[w * FF + lane * 2], r1 = ar[w * FF + lane * 2 + 1];
    float sl = v.x * a0 + v.y * a1;
    float sr = v.x * r0 + v.y * r1;
#pragma unroll
    for (int o = 16; o; o >>= 1) {
        sl += __shfl_xor_sync(0xffffffffu, sl, o);
        sr += __shfl_xor_sync(0xffffffffu, sr, o);
    }
    if (lane == 0) { g_el[n * HH + w] = sl; g_er[n * HH + w] = sr; }
}

// ---------------- attention + aggregate: block per dst, warp per head ------
__global__ __launch_bounds__(256) void k_agg(const float* __restrict__ bias, float* __restrict__ y) {
    int n = blockIdx.x;
    int tid = threadIdx.x, w = tid >> 5, lane = tid & 31;
    __shared__ float s_acc[HH][FF];
    int beg = g_rowptr[n], end = g_rowptr[n + 1];
    int deg = end - beg;
    float erw = g_er[n * HH + w];

    // pass 1: per-head max (warp-local)
    float m = -1e30f;
    for (int i = lane; i < deg; i += 32) {
        int s = g_col[beg + i];
        float e = g_el[s * HH + w] + erw;
        e = e > 0.f ? e : 0.2f * e;
        m = fmaxf(m, e);
    }
#pragma unroll
    for (int o = 16; o; o >>= 1) m = fmaxf(m, __shfl_xor_sync(0xffffffffu, m, o));

    // pass 2: exp-sum + weighted fp16 feature gather, depth-2 pipeline
    float acc0 = 0.f, acc1 = 0.f, ssum = 0.f;
    const __half2* fb = (const __half2*)g_feat;
    const int off = w * (FF / 2) + lane;           // half2 index within row
    if (deg > 0) {
        int   sA = g_col[beg];
        float eA = g_el[sA * HH + w];
        __half2 fA = fb[(size_t)sA * (CC / 2) + off];
        int sB = 0; float eB = 0.f; __half2 fBv = __float2half2_rn(0.f);
        if (deg > 1) {
            sB = g_col[beg + 1];
            eB = g_el[sB * HH + w];
            fBv = fb[(size_t)sB * (CC / 2) + off];
        }
        for (int i = 0; i < deg; i++) {
            int sC = 0; float eC = 0.f; __half2 fCv = __float2half2_rn(0.f);
            if (i + 2 < deg) {
                sC = g_col[beg + i + 2];
                eC = g_el[sC * HH + w];
                fCv = fb[(size_t)sC * (CC / 2) + off];
            }
            float e = eA + erw;
            e = e > 0.f ? e : 0.2f * e;
            float p = __expf(e - m);
            float2 ff = __half22float2(fA);
            acc0 += p * ff.x; acc1 += p * ff.y; ssum += p;
            sA = sB; eA = eB; fA = fBv;
            sB = sC; eB = eC; fBv = fCv;
        }
    }
    float inv = (deg > 0) ? 1.0f / ssum : 0.f;
    int k0 = w * FF + lane * 2;
    s_acc[w][lane * 2]     = acc0 * inv + bias[k0];
    s_acc[w][lane * 2 + 1] = acc1 * inv + bias[k0 + 1];
    __syncthreads();

    // sum heads + leaky(0.01)
    if (tid < FF) {
        float v = 0.f;
#pragma unroll
        for (int hh = 0; hh < HH; hh++) v += s_acc[hh][tid];
        v = v > 0.f ? v : 0.01f * v;
        y[(size_t)n * FF + tid] = v;
    }
}

// ---------------- launcher -------------------------------------------------
extern "C" void kernel_launch(void* const* d_in, const int* in_sizes, int n_in,
                              void* d_out, int out_size) {
    const float* x   = (const float*)d_in[0];
    const int*   src = (const int*)d_in[1];
    const int*   dst = (const int*)d_in[2];
    const float* W1  = (const float*)d_in[3];
    const float* al1 = (const float*)d_in[4];
    const float* ar1 = (const float*)d_in[5];
    const float* b1  = (const float*)d_in[6];
    const float* W2  = (const float*)d_in[7];
    const float* al2 = (const float*)d_in[8];
    const float* ar2 = (const float*)d_in[9];
    const float* b2  = (const float*)d_in[10];
    const float* W3  = (const float*)d_in[11];
    const float* al3 = (const float*)d_in[12];
    const float* ar3 = (const float*)d_in[13];
    const float* b3  = (const float*)d_in[14];
    const float* Wm  = (const float*)d_in[15];
    const float* bm  = (const float*)d_in[16];
    float* out = (float*)d_out;

    __half* feat_p;
    float* h_p;
    cudaGetSymbolAddress((void**)&feat_p, g_feat);
    cudaGetSymbolAddress((void**)&h_p, g_h);

    // CSR by dst (rebuilt every call; identical work each time)
    k_zero<<<(NN + 255) / 256, 256>>>();
    k_hist<<<(EE + 255) / 256, 256>>>(dst);
    k_scan<<<1, 1024>>>();
    k_scatter<<<(EE + 255) / 256, 256>>>(src, dst);

    dim3 gproj(CC / 64, (NN + 127) / 128);

    // layer 1 (K=128)
    k_gemm_tc<__half><<<gproj, 256>>>(x, W1, nullptr, feat_p, NN, CC, 128);
    k_eler<<<NN, 256>>>(al1, ar1);
    k_agg<<<NN, 256>>>(b1, h_p);

    // layer 2 (K=64)
    k_gemm_tc<__half><<<gproj, 256>>>(h_p, W2, nullptr, feat_p, NN, CC, 64);
    k_eler<<<NN, 256>>>(al2, ar2);
    k_agg<<<NN, 256>>>(b2, h_p);

    // layer 3 (K=64)
    k_gemm_tc<__half><<<gproj, 256>>>(h_p, W3, nullptr, feat_p, NN, CC, 64);
    k_eler<<<NN, 256>>>(al3, ar3);
    k_agg<<<NN, 256>>>(b3, h_p);

    // final linear: out = h @ Wm^T + bm  [N,OUT]
    k_gemm_tc<float><<<dim3(1, (NN + 127) / 128), 256>>>(h_p, Wm, bm, out, NN, FF, FF);
}

// round 5
// speedup vs baseline: 1.2948x; 1.2948x over previous
#include <cuda_runtime.h>
#include <cuda_fp16.h>
#include <cstdint>

#define NN 50000
#define EE 800000
#define CC 512     // H*HID
#define HH 8
#define FF 64

// ---------------- scratch (device globals; no allocation allowed) ----------
__device__ __half g_feat[(size_t)NN * CC];  // 51.2 MB projected features (fp16)
__device__ float g_el[NN * HH];
__device__ float g_er[NN * HH];
__device__ float g_h[NN * FF];              // layer activations (fp32)
__device__ int   g_rowptr[NN + 1];
__device__ int   g_cnt[NN];
__device__ int   g_fill[NN];
__device__ int   g_col[EE];                 // src ids grouped by dst

// ---------------- CSR build ------------------------------------------------
__global__ void k_zero() {
    int i = blockIdx.x * blockDim.x + threadIdx.x;
    if (i < NN) { g_cnt[i] = 0; g_fill[i] = 0; }
}

__global__ void k_hist(const int* __restrict__ dst) {
    int e = blockIdx.x * blockDim.x + threadIdx.x;
    if (e < EE) atomicAdd(&g_cnt[dst[e]], 1);
}

__global__ void k_scan() {
    __shared__ int sh[1024];
    __shared__ int s_off;
    int tid = threadIdx.x;
    if (tid == 0) s_off = 0;
    __syncthreads();
    for (int base = 0; base < NN; base += 1024) {
        int idx = base + tid;
        int orig = (idx < NN) ? g_cnt[idx] : 0;
        int v = orig;
        sh[tid] = v;
        __syncthreads();
        for (int off = 1; off < 1024; off <<= 1) {
            int add = (tid >= off) ? sh[tid - off] : 0;
            __syncthreads();
            v += add; sh[tid] = v;
            __syncthreads();
        }
        int myoff = s_off;
        if (idx < NN) g_rowptr[idx] = myoff + (v - orig);
        __syncthreads();
        if (tid == 1023) s_off = myoff + v;
        __syncthreads();
    }
    if (tid == 0) g_rowptr[NN] = s_off;
}

__global__ void k_scatter(const int* __restrict__ src, const int* __restrict__ dst) {
    int e = blockIdx.x * blockDim.x + threadIdx.x;
    if (e < EE) {
        int d = dst[e];
        int pos = g_rowptr[d] + atomicAdd(&g_fill[d], 1);
        g_col[pos] = src[e];
    }
}

// ---------------- tf32 tensor-core GEMM ------------------------------------
// C[M,NCol] = A[M,K] @ B[NCol,K]^T (+bias).  K multiple of 32, NCol mult of 64.
__device__ __forceinline__ uint32_t f2tf(float f) {
    uint32_t r;
    asm("cvt.rna.tf32.f32 %0, %1;" : "=r"(r) : "f"(f));
    return r;
}

__device__ __forceinline__ void store_c(float* C, size_t idx, float v) { C[idx] = v; }
__device__ __forceinline__ void store_c(__half* C, size_t idx, float v) { C[idx] = __float2half_rn(v); }

template <typename OutT>
__global__ __launch_bounds__(256, 2) void k_gemm_tc(
    const float* __restrict__ A, const float* __restrict__ B,
    const float* __restrict__ bias, OutT* __restrict__ C,
    int M, int NCol, int K)
{
    // fragment-layout smem: [kstep(4)][tile(8)][lane(32)][quad]
    __shared__ uint32_t As2[4 * 8 * 32 * 4];   // 16 KB
    __shared__ uint32_t Bs2[4 * 8 * 32 * 2];   //  8 KB
    const int tid = threadIdx.x;
    const int lane = tid & 31, wid = tid >> 5;
    const int wm = wid & 3, wn = wid >> 2;          // warp grid 4(M) x 2(N)
    const int m0 = blockIdx.y * 128, n0 = blockIdx.x * 64;

    float acc[2][4][4];
#pragma unroll
    for (int im = 0; im < 2; im++)
#pragma unroll
        for (int in = 0; in < 4; in++)
#pragma unroll
            for (int q = 0; q < 4; q++) acc[im][in][q] = 0.f;

    float4 rA[4], rB[2];

    // prefetch slab 0
#pragma unroll
    for (int i = 0; i < 4; i++) {
        int idx = tid + 256 * i;
        int row = idx >> 3, c0 = (idx & 7) << 2;
        int gr = m0 + row;
        rA[i] = (gr < M) ? *(const float4*)(A + (size_t)gr * K + c0)
                         : make_float4(0.f, 0.f, 0.f, 0.f);
    }
#pragma unroll
    for (int i = 0; i < 2; i++) {
        int idx = tid + 256 * i;
        int row = idx >> 3, c0 = (idx & 7) << 2;
        rB[i] = *(const float4*)(B + (size_t)(n0 + row) * K + c0);
    }

    for (int kt = 0; kt < K; kt += 32) {
        __syncthreads();
        // ---- store A fragments (pre-permuted, tf32-converted) ----
#pragma unroll
        for (int i = 0; i < 4; i++) {
            int idx = tid + 256 * i;
            int row = idx >> 3, c0 = (idx & 7) << 2;
            int mt = row >> 4, rr = row & 15;
            int q1 = rr >> 3, lrow = rr & 7;
            int ks = c0 >> 3, q0 = (c0 >> 2) & 1;
            int quad = q1 * 2 + q0;
            int base = (ks * 8 + mt) * 32;
            int lb = lrow * 4 + ks * 8;
            As2[(base + ((lb + 0) & 31)) * 4 + quad] = f2tf(rA[i].x);
            As2[(base + ((lb + 1) & 31)) * 4 + quad] = f2tf(rA[i].y);
            As2[(base + ((lb + 2) & 31)) * 4 + quad] = f2tf(rA[i].z);
            As2[(base + ((lb + 3) & 31)) * 4 + quad] = f2tf(rA[i].w);
        }
        // ---- store B fragments ----
#pragma unroll
        for (int i = 0; i < 2; i++) {
            int idx = tid + 256 * i;
            int row = idx >> 3, c0 = (idx & 7) << 2;
            int nt = row >> 3, ln = row & 7;
            int ks = c0 >> 3, q0 = (c0 >> 2) & 1;
            int base = (ks * 8 + nt) * 32;
            int lb = ln * 4 + ks * 8;
            Bs2[(base + ((lb + 0) & 31)) * 2 + q0] = f2tf(rB[i].x);
            Bs2[(base + ((lb + 1) & 31)) * 2 + q0] = f2tf(rB[i].y);
            Bs2[(base + ((lb + 2) & 31)) * 2 + q0] = f2tf(rB[i].z);
            Bs2[(base + ((lb + 3) & 31)) * 2 + q0] = f2tf(rB[i].w);
        }
        __syncthreads();

        // ---- prefetch next slab (overlaps with mma below) ----
        if (kt + 32 < K) {
#pragma unroll
            for (int i = 0; i < 4; i++) {
                int idx = tid + 256 * i;
                int row = idx >> 3, c0 = (idx & 7) << 2;
                int gr = m0 + row;
                rA[i] = (gr < M) ? *(const float4*)(A + (size_t)gr * K + kt + 32 + c0)
                                 : make_float4(0.f, 0.f, 0.f, 0.f);
            }
#pragma unroll
            for (int i = 0; i < 2; i++) {
                int idx = tid + 256 * i;
                int row = idx >> 3, c0 = (idx & 7) << 2;
                rB[i] = *(const float4*)(B + (size_t)(n0 + row) * K + kt + 32 + c0);
            }
        }

        // ---- compute: 4 k-steps x 8 mma per warp ----
#pragma unroll
        for (int ks = 0; ks < 4; ks++) {
            int ll = (lane + ks * 8) & 31;
            uint32_t a[2][4];
#pragma unroll
            for (int im = 0; im < 2; im++) {
                uint4 v = *(const uint4*)(As2 + ((ks * 8 + wm * 2 + im) * 32 + ll) * 4);
                a[im][0] = v.x; a[im][2] = v.y; a[im][1] = v.z; a[im][3] = v.w;
            }
            uint32_t b[4][2];
#pragma unroll
            for (int in = 0; in < 4; in++) {
                uint2 v = *(const uint2*)(Bs2 + ((ks * 8 + wn * 4 + in) * 32 + ll) * 2);
                b[in][0] = v.x; b[in][1] = v.y;
            }
#pragma unroll
            for (int im = 0; im < 2; im++)
#pragma unroll
                for (int in = 0; in < 4; in++)
                    asm volatile(
                        "mma.sync.aligned.m16n8k8.row.col.f32.tf32.tf32.f32 "
                        "{%0,%1,%2,%3},{%4,%5,%6,%7},{%8,%9},{%0,%1,%2,%3};"
                        : "+f"(acc[im][in][0]), "+f"(acc[im][in][1]),
                          "+f"(acc[im][in][2]), "+f"(acc[im][in][3])
                        : "r"(a[im][0]), "r"(a[im][1]), "r"(a[im][2]), "r"(a[im][3]),
                          "r"(b[in][0]), "r"(b[in][1]));
        }
    }

    // ---- epilogue ----
    int gid = lane >> 2, tig = lane & 3;
#pragma unroll
    for (int im = 0; im < 2; im++) {
        int r = m0 + wm * 32 + im * 16 + gid;
#pragma unroll
        for (int in = 0; in < 4; in++) {
            int c = n0 + wn * 32 + in * 8 + tig * 2;
            float b0v = bias ? bias[c] : 0.f;
            float b1v = bias ? bias[c + 1] : 0.f;
            if (r < M) {
                store_c(C, (size_t)r * NCol + c,     acc[im][in][0] + b0v);
                store_c(C, (size_t)r * NCol + c + 1, acc[im][in][1] + b1v);
            }
            if (r + 8 < M) {
                store_c(C, (size_t)(r + 8) * NCol + c,     acc[im][in][2] + b0v);
                store_c(C, (size_t)(r + 8) * NCol + c + 1, acc[im][in][3] + b1v);
            }
        }
    }
}

// ---------------- el/er: per-(node,head) dot of feat with al/ar ------------
__global__ void k_eler(const float* __restrict__ al, const float* __restrict__ ar) {
    int n = blockIdx.x;
    int w = threadIdx.x >> 5, lane = threadIdx.x & 31;
    const __half2* f = (const __half2*)g_feat + (size_t)n * (CC / 2) + w * (FF / 2);
    float2 v = __half22float2(f[lane]);
    float a0 = al[w * FF + lane * 2], a1 = al[w * FF + lane * 2 + 1];
    float r0 = ar[w * FF + lane * 2], r1 = ar[w * FF + lane * 2 + 1];
    float sl = v.x * a0 + v.y * a1;
    float sr = v.x * r0 + v.y * r1;
#pragma unroll
    for (int o = 16; o; o >>= 1) {
        sl += __shfl_xor_sync(0xffffffffu, sl, o);
        sr += __shfl_xor_sync(0xffffffffu, sr, o);
    }
    if (lane == 0) { g_el[n * HH + w] = sl; g_er[n * HH + w] = sr; }
}

// ---------------- attention + aggregate -----------------------------------
// Block per dst node, warp per head. Within a warp: sub = lane>>3 processes
// edge (i*4+sub); j = lane&7 owns features [j*8, j*8+8) as one 16B uint4.
// No max pass: exp(e)/sum(exp(e)) == softmax(e) exactly; |e| is O(1) here.
__global__ __launch_bounds__(256) void k_agg(const float* __restrict__ bias, float* __restrict__ y) {
    int n = blockIdx.x;
    int tid = threadIdx.x, w = tid >> 5, lane = tid & 31;
    int sub = lane >> 3, j = lane & 7;
    __shared__ float s_acc[HH][FF];
    int beg = g_rowptr[n], end = g_rowptr[n + 1];
    int deg = end - beg;
    float erw = g_er[n * HH + w];

    float acc[8] = {};
    float ssum = 0.f;
    const __half* fbase = g_feat;
    int niter = (deg + 3) >> 2;
    for (int i = 0; i < niter; i++) {
        int ei = beg + i * 4 + sub;
        int s = 0; float p = 0.f;
        if (j == 0 && ei < end) {
            s = __ldg(&g_col[ei]);
            float e = __ldg(&g_el[s * HH + w]) + erw;
            e = e > 0.f ? e : 0.2f * e;
            p = __expf(e);
        }
        s = __shfl_sync(0xffffffffu, s, lane & 24);
        p = __shfl_sync(0xffffffffu, p, lane & 24);
        uint4 v = *(const uint4*)(fbase + (size_t)s * CC + w * FF + j * 8);
        float2 f0 = __half22float2(*(const __half2*)&v.x);
        float2 f1 = __half22float2(*(const __half2*)&v.y);
        float2 f2 = __half22float2(*(const __half2*)&v.z);
        float2 f3 = __half22float2(*(const __half2*)&v.w);
        acc[0] += p * f0.x; acc[1] += p * f0.y;
        acc[2] += p * f1.x; acc[3] += p * f1.y;
        acc[4] += p * f2.x; acc[5] += p * f2.y;
        acc[6] += p * f3.x; acc[7] += p * f3.y;
        ssum += p;
    }
    // reduce the 4 edge-subgroups (lane bits 3,4)
#pragma unroll
    for (int o = 8; o <= 16; o <<= 1) {
        ssum += __shfl_xor_sync(0xffffffffu, ssum, o);
#pragma unroll
        for (int k = 0; k < 8; k++) acc[k] += __shfl_xor_sync(0xffffffffu, acc[k], o);
    }
    float inv = (deg > 0) ? 1.0f / ssum : 0.f;
    if (sub == 0) {
#pragma unroll
        for (int k = 0; k < 8; k++)
            s_acc[w][j * 8 + k] = acc[k] * inv + bias[w * FF + j * 8 + k];
    }
    __syncthreads();

    // sum heads + leaky(0.01)
    if (tid < FF) {
        float v = 0.f;
#pragma unroll
        for (int hh = 0; hh < HH; hh++) v += s_acc[hh][tid];
        v = v > 0.f ? v : 0.01f * v;
        y[(size_t)n * FF + tid] = v;
    }
}

// ---------------- launcher -------------------------------------------------
extern "C" void kernel_launch(void* const* d_in, const int* in_sizes, int n_in,
                              void* d_out, int out_size) {
    const float* x   = (const float*)d_in[0];
    const int*   src = (const int*)d_in[1];
    const int*   dst = (const int*)d_in[2];
    const float* W1  = (const float*)d_in[3];
    const float* al1 = (const float*)d_in[4];
    const float* ar1 = (const float*)d_in[5];
    const float* b1  = (const float*)d_in[6];
    const float* W2  = (const float*)d_in[7];
    const float* al2 = (const float*)d_in[8];
    const float* ar2 = (const float*)d_in[9];
    const float* b2  = (const float*)d_in[10];
    const float* W3  = (const float*)d_in[11];
    const float* al3 = (const float*)d_in[12];
    const float* ar3 = (const float*)d_in[13];
    const float* b3  = (const float*)d_in[14];
    const float* Wm  = (const float*)d_in[15];
    const float* bm  = (const float*)d_in[16];
    float* out = (float*)d_out;

    __half* feat_p;
    float* h_p;
    cudaGetSymbolAddress((void**)&feat_p, g_feat);
    cudaGetSymbolAddress((void**)&h_p, g_h);

    // CSR by dst (rebuilt every call; identical work each time)
    k_zero<<<(NN + 255) / 256, 256>>>();
    k_hist<<<(EE + 255) / 256, 256>>>(dst);
    k_scan<<<1, 1024>>>();
    k_scatter<<<(EE + 255) / 256, 256>>>(src, dst);

    dim3 gproj(CC / 64, (NN + 127) / 128);

    // layer 1 (K=128)
    k_gemm_tc<__half><<<gproj, 256>>>(x, W1, nullptr, feat_p, NN, CC, 128);
    k_eler<<<NN, 256>>>(al1, ar1);
    k_agg<<<NN, 256>>>(b1, h_p);

    // layer 2 (K=64)
    k_gemm_tc<__half><<<gproj, 256>>>(h_p, W2, nullptr, feat_p, NN, CC, 64);
    k_eler<<<NN, 256>>>(al2, ar2);
    k_agg<<<NN, 256>>>(b2, h_p);

    // layer 3 (K=64)
    k_gemm_tc<__half><<<gproj, 256>>>(h_p, W3, nullptr, feat_p, NN, CC, 64);
    k_eler<<<NN, 256>>>(al3, ar3);
    k_agg<<<NN, 256>>>(b3, h_p);

    // final linear: out = h @ Wm^T + bm  [N,OUT]
    k_gemm_tc<float><<<dim3(1, (NN + 127) / 128), 256>>>(h_p, Wm, bm, out, NN, FF, FF);
}

// round 8
// speedup vs baseline: 1.3838x; 1.0687x over previous
#include <cuda_runtime.h>
#include <cuda_fp16.h>
#include <cstdint>

#define NN 50000
#define EE 800000
#define CC 512     // H*HID
#define HH 8
#define FF 64

// ---------------- scratch (device globals; no allocation allowed) ----------
__device__ __half g_feat[(size_t)NN * CC];  // 51.2 MB projected features (fp16)
__device__ float g_el[NN * HH];
__device__ float g_er[NN * HH];
__device__ float g_p[(size_t)EE * HH];      // 25.6 MB per-edge-head exp weights
__device__ float g_h[NN * FF];              // layer activations (fp32)
__device__ int   g_rowptr[NN + 1];
__device__ int   g_cnt[NN];
__device__ int   g_fill[NN];
__device__ int   g_col[EE];                 // src ids grouped by dst (CSR order)
__device__ int   g_dstE[EE];                // dst id per CSR position

// ---------------- CSR build ------------------------------------------------
__global__ void k_zero() {
    int i = blockIdx.x * blockDim.x + threadIdx.x;
    if (i < NN) { g_cnt[i] = 0; g_fill[i] = 0; }
}

__global__ void k_hist(const int* __restrict__ dst) {
    int e = blockIdx.x * blockDim.x + threadIdx.x;
    if (e < EE) atomicAdd(&g_cnt[dst[e]], 1);
}

__global__ void k_scan() {
    __shared__ int sh[1024];
    __shared__ int s_off;
    int tid = threadIdx.x;
    if (tid == 0) s_off = 0;
    __syncthreads();
    for (int base = 0; base < NN; base += 1024) {
        int idx = base + tid;
        int orig = (idx < NN) ? g_cnt[idx] : 0;
        int v = orig;
        sh[tid] = v;
        __syncthreads();
        for (int off = 1; off < 1024; off <<= 1) {
            int add = (tid >= off) ? sh[tid - off] : 0;
            __syncthreads();
            v += add; sh[tid] = v;
            __syncthreads();
        }
        int myoff = s_off;
        if (idx < NN) g_rowptr[idx] = myoff + (v - orig);
        __syncthreads();
        if (tid == 1023) s_off = myoff + v;
        __syncthreads();
    }
    if (tid == 0) g_rowptr[NN] = s_off;
}

__global__ void k_scatter(const int* __restrict__ src, const int* __restrict__ dst) {
    int e = blockIdx.x * blockDim.x + threadIdx.x;
    if (e < EE) {
        int d = dst[e];
        int pos = g_rowptr[d] + atomicAdd(&g_fill[d], 1);
        g_col[pos] = src[e];
        g_dstE[pos] = d;
    }
}

// ---------------- tf32 tensor-core GEMM + fused el/er ----------------------
// C[M,NCol] = A[M,K] @ B[NCol,K]^T (+bias).  K multiple of 32, NCol mult of 64.
// If al/ar non-null: NCol block (64 cols) == one head; epilogue computes
// el[row,head], er[row,head] from the fp32 accumulators.
__device__ __forceinline__ uint32_t f2tf(float f) {
    uint32_t r;
    asm("cvt.rna.tf32.f32 %0, %1;" : "=r"(r) : "f"(f));
    return r;
}

__device__ __forceinline__ void store_c(float* C, size_t idx, float v) { C[idx] = v; }
__device__ __forceinline__ void store_c(__half* C, size_t idx, float v) { C[idx] = __float2half_rn(v); }

template <typename OutT>
__global__ __launch_bounds__(256, 2) void k_gemm_tc(
    const float* __restrict__ A, const float* __restrict__ B,
    const float* __restrict__ bias, OutT* __restrict__ C,
    const float* __restrict__ al, const float* __restrict__ ar,
    int M, int NCol, int K)
{
    // fragment-layout smem: [kstep(4)][tile(8)][lane(32)][quad]
    __shared__ uint32_t As2[4 * 8 * 32 * 4];   // 16 KB
    __shared__ uint32_t Bs2[4 * 8 * 32 * 2];   //  8 KB
    __shared__ float s_el[128], s_er[128];
    const int tid = threadIdx.x;
    const int lane = tid & 31, wid = tid >> 5;
    const int wm = wid & 3, wn = wid >> 2;          // warp grid 4(M) x 2(N)
    const int m0 = blockIdx.y * 128, n0 = blockIdx.x * 64;

    float acc[2][4][4];
#pragma unroll
    for (int im = 0; im < 2; im++)
#pragma unroll
        for (int in = 0; in < 4; in++)
#pragma unroll
            for (int q = 0; q < 4; q++) acc[im][in][q] = 0.f;

    float4 rA[4], rB[2];

    // prefetch slab 0
#pragma unroll
    for (int i = 0; i < 4; i++) {
        int idx = tid + 256 * i;
        int row = idx >> 3, c0 = (idx & 7) << 2;
        int gr = m0 + row;
        rA[i] = (gr < M) ? *(const float4*)(A + (size_t)gr * K + c0)
                         : make_float4(0.f, 0.f, 0.f, 0.f);
    }
#pragma unroll
    for (int i = 0; i < 2; i++) {
        int idx = tid + 256 * i;
        int row = idx >> 3, c0 = (idx & 7) << 2;
        rB[i] = *(const float4*)(B + (size_t)(n0 + row) * K + c0);
    }

    for (int kt = 0; kt < K; kt += 32) {
        __syncthreads();
        // ---- store A fragments (pre-permuted, tf32-converted) ----
#pragma unroll
        for (int i = 0; i < 4; i++) {
            int idx = tid + 256 * i;
            int row = idx >> 3, c0 = (idx & 7) << 2;
            int mt = row >> 4, rr = row & 15;
            int q1 = rr >> 3, lrow = rr & 7;
            int ks = c0 >> 3, q0 = (c0 >> 2) & 1;
            int quad = q1 * 2 + q0;
            int base = (ks * 8 + mt) * 32;
            int lb = lrow * 4 + ks * 8;
            As2[(base + ((lb + 0) & 31)) * 4 + quad] = f2tf(rA[i].x);
            As2[(base + ((lb + 1) & 31)) * 4 + quad] = f2tf(rA[i].y);
            As2[(base + ((lb + 2) & 31)) * 4 + quad] = f2tf(rA[i].z);
            As2[(base + ((lb + 3) & 31)) * 4 + quad] = f2tf(rA[i].w);
        }
        // ---- store B fragments ----
#pragma unroll
        for (int i = 0; i < 2; i++) {
            int idx = tid + 256 * i;
            int row = idx >> 3, c0 = (idx & 7) << 2;
            int nt = row >> 3, ln = row & 7;
            int ks = c0 >> 3, q0 = (c0 >> 2) & 1;
            int base = (ks * 8 + nt) * 32;
            int lb = ln * 4 + ks * 8;
            Bs2[(base + ((lb + 0) & 31)) * 2 + q0] = f2tf(rB[i].x);
            Bs2[(base + ((lb + 1) & 31)) * 2 + q0] = f2tf(rB[i].y);
            Bs2[(base + ((lb + 2) & 31)) * 2 + q0] = f2tf(rB[i].z);
            Bs2[(base + ((lb + 3) & 31)) * 2 + q0] = f2tf(rB[i].w);
        }
        __syncthreads();

        // ---- prefetch next slab (overlaps with mma below) ----
        if (kt + 32 < K) {
#pragma unroll
            for (int i = 0; i < 4; i++) {
                int idx = tid + 256 * i;
                int row = idx >> 3, c0 = (idx & 7) << 2;
                int gr = m0 + row;
                rA[i] = (gr < M) ? *(const float4*)(A + (size_t)gr * K + kt + 32 + c0)
                                 : make_float4(0.f, 0.f, 0.f, 0.f);
            }
#pragma unroll
            for (int i = 0; i < 2; i++) {
                int idx = tid + 256 * i;
                int row = idx >> 3, c0 = (idx & 7) << 2;
                rB[i] = *(const float4*)(B + (size_t)(n0 + row) * K + kt + 32 + c0);
            }
        }

        // ---- compute: 4 k-steps x 8 mma per warp ----
#pragma unroll
        for (int ks = 0; ks < 4; ks++) {
            int ll = (lane + ks * 8) & 31;
            uint32_t a[2][4];
#pragma unroll
            for (int im = 0; im < 2; im++) {
                uint4 v = *(const uint4*)(As2 + ((ks * 8 + wm * 2 + im) * 32 + ll) * 4);
                a[im][0] = v.x; a[im][2] = v.y; a[im][1] = v.z; a[im][3] = v.w;
            }
            uint32_t b[4][2];
#pragma unroll
            for (int in = 0; in < 4; in++) {
                uint2 v = *(const uint2*)(Bs2 + ((ks * 8 + wn * 4 + in) * 32 + ll) * 2);
                b[in][0] = v.x; b[in][1] = v.y;
            }
#pragma unroll
            for (int im = 0; im < 2; im++)
#pragma unroll
                for (int in = 0; in < 4; in++)
                    asm volatile(
                        "mma.sync.aligned.m16n8k8.row.col.f32.tf32.tf32.f32 "
                        "{%0,%1,%2,%3},{%4,%5,%6,%7},{%8,%9},{%0,%1,%2,%3};"
                        : "+f"(acc[im][in][0]), "+f"(acc[im][in][1]),
                          "+f"(acc[im][in][2]), "+f"(acc[im][in][3])
                        : "r"(a[im][0]), "r"(a[im][1]), "r"(a[im][2]), "r"(a[im][3]),
                          "r"(b[in][0]), "r"(b[in][1]));
        }
    }

    // ---- epilogue: store C ----
    int gid = lane >> 2, tig = lane & 3;
#pragma unroll
    for (int im = 0; im < 2; im++) {
        int r = m0 + wm * 32 + im * 16 + gid;
#pragma unroll
        for (int in = 0; in < 4; in++) {
            int c = n0 + wn * 32 + in * 8 + tig * 2;
            float b0v = bias ? bias[c] : 0.f;
            float b1v = bias ? bias[c + 1] : 0.f;
            if (r < M) {
                store_c(C, (size_t)r * NCol + c,     acc[im][in][0] + b0v);
                store_c(C, (size_t)r * NCol + c + 1, acc[im][in][1] + b1v);
            }
            if (r + 8 < M) {
                store_c(C, (size_t)(r + 8) * NCol + c,     acc[im][in][2] + b0v);
                store_c(C, (size_t)(r + 8) * NCol + c + 1, acc[im][in][3] + b1v);
            }
        }
    }

    // ---- fused el/er: this block's 64 cols == head (blockIdx.x) ----
    if (al != nullptr) {
        int head = blockIdx.x;
        const float* alh = al + head * FF;
        const float* arh = ar + head * FF;
        float sl[2][2] = {}, sr[2][2] = {};   // [im][0: row r, 1: row r+8]
#pragma unroll
        for (int im = 0; im < 2; im++)
#pragma unroll
            for (int in = 0; in < 4; in++) {
                int cc0 = wn * 32 + in * 8 + tig * 2;
                float a0 = alh[cc0], a1 = alh[cc0 + 1];
                float r0 = arh[cc0], r1 = arh[cc0 + 1];
                sl[im][0] += acc[im][in][0] * a0 + acc[im][in][1] * a1;
                sl[im][1] += acc[im][in][2] * a0 + acc[im][in][3] * a1;
                sr[im][0] += acc[im][in][0] * r0 + acc[im][in][1] * r1;
                sr[im][1] += acc[im][in][2] * r0 + acc[im][in][3] * r1;
            }
        // reduce over tig (lane bits 0,1)
#pragma unroll
        for (int o = 1; o <= 2; o <<= 1)
#pragma unroll
            for (int im = 0; im < 2; im++)
#pragma unroll
                for (int hq = 0; hq < 2; hq++) {
                    sl[im][hq] += __shfl_xor_sync(0xffffffffu, sl[im][hq], o);
                    sr[im][hq] += __shfl_xor_sync(0xffffffffu, sr[im][hq], o);
                }
        __syncthreads();   // As2/Bs2 done; reuse barrier for s_el staging
        if (wn == 0 && tig == 0) {
#pragma unroll
            for (int im = 0; im < 2; im++) {
                int rl = wm * 32 + im * 16 + gid;
                s_el[rl] = sl[im][0];     s_er[rl] = sr[im][0];
                s_el[rl + 8] = sl[im][1]; s_er[rl + 8] = sr[im][1];
            }
        }
        __syncthreads();
        if (wn == 1 && tig == 0) {
#pragma unroll
            for (int im = 0; im < 2; im++) {
                int rl = wm * 32 + im * 16 + gid;
                int r = m0 + rl;
                if (r < M) {
                    g_el[r * HH + head] = s_el[rl] + sl[im][0];
                    g_er[r * HH + head] = s_er[rl] + sr[im][0];
                }
                if (r + 8 < M) {
                    g_el[(r + 8) * HH + head] = s_el[rl + 8] + sl[im][1];
                    g_er[(r + 8) * HH + head] = s_er[rl + 8] + sr[im][1];
                }
            }
        }
    }
}

// ---------------- per-(edge,head) attention weight -------------------------
// p[pos,h] = exp(leaky(el[src]+er[dst])); CSR-ordered, coalesced write.
__global__ __launch_bounds__(256) void k_edgeP() {
    int i = blockIdx.x * blockDim.x + threadIdx.x;   // over EE*HH
    if (i >= EE * HH) return;
    int pos = i >> 3, h = i & 7;
    int s = __ldg(&g_col[pos]);
    int d = __ldg(&g_dstE[pos]);
    float e = __ldg(&g_el[s * HH + h]) + __ldg(&g_er[d * HH + h]);
    e = e > 0.f ? e : 0.2f * e;
    g_p[i] = __expf(e);
}

// ---------------- aggregate: block per dst, warp per head ------------------
// sub = lane>>3 handles edge i*4+sub; j = lane&7 owns 8 feats (one uint4).
// col/p loads are sub-uniform broadcasts (no shfl, no expf in loop).
__global__ __launch_bounds__(256) void k_agg(const float* __restrict__ bias, float* __restrict__ y) {
    int n = blockIdx.x;
    int tid = threadIdx.x, w = tid >> 5, lane = tid & 31;
    int sub = lane >> 3, j = lane & 7;
    __shared__ float s_acc[HH][FF];
    int beg = g_rowptr[n], end = g_rowptr[n + 1];
    int deg = end - beg;

    float acc[8] = {};
    float ssum = 0.f;
    int niter = (deg + 3) >> 2;
    for (int i = 0; i < niter; i++) {
        int ei = beg + i * 4 + sub;
        bool valid = ei < end;
        int eic = valid ? ei : beg;
        int s = __ldg(&g_col[eic]);
        float p = valid ? __ldg(&g_p[(size_t)eic * HH + w]) : 0.f;
        uint4 v = *(const uint4*)(g_feat + (size_t)s * CC + w * FF + j * 8);
        float2 f0 = __half22float2(*(const __half2*)&v.x);
        float2 f1 = __half22float2(*(const __half2*)&v.y);
        float2 f2 = __half22float2(*(const __half2*)&v.z);
        float2 f3 = __half22float2(*(const __half2*)&v.w);
        acc[0] += p * f0.x; acc[1] += p * f0.y;
        acc[2] += p * f1.x; acc[3] += p * f1.y;
        acc[4] += p * f2.x; acc[5] += p * f2.y;
        acc[6] += p * f3.x; acc[7] += p * f3.y;
        ssum += p;
    }
    // reduce the 4 edge-subgroups (lane bits 3,4)
#pragma unroll
    for (int o = 8; o <= 16; o <<= 1) {
        ssum += __shfl_xor_sync(0xffffffffu, ssum, o);
#pragma unroll
        for (int k = 0; k < 8; k++) acc[k] += __shfl_xor_sync(0xffffffffu, acc[k], o);
    }
    float inv = (deg > 0) ? 1.0f / ssum : 0.f;
    if (sub == 0) {
#pragma unroll
        for (int k = 0; k < 8; k++)
            s_acc[w][j * 8 + k] = acc[k] * inv + bias[w * FF + j * 8 + k];
    }
    __syncthreads();

    // sum heads + leaky(0.01)
    if (tid < FF) {
        float v = 0.f;
#pragma unroll
        for (int hh = 0; hh < HH; hh++) v += s_acc[hh][tid];
        v = v > 0.f ? v : 0.01f * v;
        y[(size_t)n * FF + tid] = v;
    }
}

// ---------------- launcher -------------------------------------------------
extern "C" void kernel_launch(void* const* d_in, const int* in_sizes, int n_in,
                              void* d_out, int out_size) {
    const float* x   = (const float*)d_in[0];
    const int*   src = (const int*)d_in[1];
    const int*   dst = (const int*)d_in[2];
    const float* W1  = (const float*)d_in[3];
    const float* al1 = (const float*)d_in[4];
    const float* ar1 = (const float*)d_in[5];
    const float* b1  = (const float*)d_in[6];
    const float* W2  = (const float*)d_in[7];
    const float* al2 = (const float*)d_in[8];
    const float* ar2 = (const float*)d_in[9];
    const float* b2  = (const float*)d_in[10];
    const float* W3  = (const float*)d_in[11];
    const float* al3 = (const float*)d_in[12];
    const float* ar3 = (const float*)d_in[13];
    const float* b3  = (const float*)d_in[14];
    const float* Wm  = (const float*)d_in[15];
    const float* bm  = (const float*)d_in[16];
    float* out = (float*)d_out;

    __half* feat_p;
    float* h_p;
    cudaGetSymbolAddress((void**)&feat_p, g_feat);
    cudaGetSymbolAddress((void**)&h_p, g_h);

    // CSR by dst (rebuilt every call; identical work each time)
    k_zero<<<(NN + 255) / 256, 256>>>();
    k_hist<<<(EE + 255) / 256, 256>>>(dst);
    k_scan<<<1, 1024>>>();
    k_scatter<<<(EE + 255) / 256, 256>>>(src, dst);

    dim3 gproj(CC / 64, (NN + 127) / 128);
    int gep = (EE * HH + 255) / 256;

    // layer 1 (K=128)
    k_gemm_tc<__half><<<gproj, 256>>>(x, W1, nullptr, feat_p, al1, ar1, NN, CC, 128);
    k_edgeP<<<gep, 256>>>();
    k_agg<<<NN, 256>>>(b1, h_p);

    // layer 2 (K=64)
    k_gemm_tc<__half><<<gproj, 256>>>(h_p, W2, nullptr, feat_p, al2, ar2, NN, CC, 64);
    k_edgeP<<<gep, 256>>>();
    k_agg<<<NN, 256>>>(b2, h_p);

    // layer 3 (K=64)
    k_gemm_tc<__half><<<gproj, 256>>>(h_p, W3, nullptr, feat_p, al3, ar3, NN, CC, 64);
    k_edgeP<<<gep, 256>>>();
    k_agg<<<NN, 256>>>(b3, h_p);

    // final linear: out = h @ Wm^T + bm  [N,OUT]
    k_gemm_tc<float><<<dim3(1, (NN + 127) / 128), 256>>>(h_p, Wm, bm, out,
                                                         nullptr, nullptr, NN, FF, FF);
}

// round 9
// speedup vs baseline: 1.6680x; 1.2054x over previous
#include <cuda_runtime.h>
#include <cuda_fp16.h>
#include <cstdint>

#define NN 50000
#define EE 800000
#define CC 512     // H*HID
#define HH 8
#define FF 64

// ---------------- scratch (device globals; no allocation allowed) ----------
__device__ __half g_feat[(size_t)NN * CC];  // 51.2 MB projected features (fp16)
__device__ float g_el[NN * HH];
__device__ float g_er[NN * HH];
__device__ float g_h[NN * FF];              // layer activations (fp32)
__device__ int   g_rowptr[NN + 1];
__device__ int   g_cnt[NN];
__device__ int   g_fill[NN];
__device__ int   g_col[EE];                 // src ids grouped by dst (CSR order)

// ---------------- CSR build ------------------------------------------------
__global__ void k_zero() {
    int i = blockIdx.x * blockDim.x + threadIdx.x;
    if (i < NN) { g_cnt[i] = 0; g_fill[i] = 0; }
}

__global__ void k_hist(const int* __restrict__ dst) {
    int e = blockIdx.x * blockDim.x + threadIdx.x;
    if (e < EE) atomicAdd(&g_cnt[dst[e]], 1);
}

__global__ void k_scan() {
    __shared__ int sh[1024];
    __shared__ int s_off;
    int tid = threadIdx.x;
    if (tid == 0) s_off = 0;
    __syncthreads();
    for (int base = 0; base < NN; base += 1024) {
        int idx = base + tid;
        int orig = (idx < NN) ? g_cnt[idx] : 0;
        int v = orig;
        sh[tid] = v;
        __syncthreads();
        for (int off = 1; off < 1024; off <<= 1) {
            int add = (tid >= off) ? sh[tid - off] : 0;
            __syncthreads();
            v += add; sh[tid] = v;
            __syncthreads();
        }
        int myoff = s_off;
        if (idx < NN) g_rowptr[idx] = myoff + (v - orig);
        __syncthreads();
        if (tid == 1023) s_off = myoff + v;
        __syncthreads();
    }
    if (tid == 0) g_rowptr[NN] = s_off;
}

__global__ void k_scatter(const int* __restrict__ src, const int* __restrict__ dst) {
    int e = blockIdx.x * blockDim.x + threadIdx.x;
    if (e < EE) {
        int d = dst[e];
        int pos = g_rowptr[d] + atomicAdd(&g_fill[d], 1);
        g_col[pos] = src[e];
    }
}

// ---------------- fp16 tensor-core GEMM + fused el/er ----------------------
// C[M,NCol] = A[M,K] @ B[NCol,K]^T (+bias).  K multiple of 32, NCol mult of 64.
// Block tile 128x64, 8 warps (4M x 2N), warp tile 32x32, mma m16n8k16.
// If al/ar non-null: the 64-col block == one head; epilogue emits el/er.
__device__ __forceinline__ uint32_t pk(float x, float y) {
    __half2 h = __floats2half2_rn(x, y);
    return *reinterpret_cast<uint32_t*>(&h);
}

__device__ __forceinline__ void store_c(float* C, size_t idx, float v) { C[idx] = v; }
__device__ __forceinline__ void store_c(__half* C, size_t idx, float v) { C[idx] = __float2half_rn(v); }

template <typename OutT>
__global__ __launch_bounds__(256, 2) void k_gemm_tc(
    const float* __restrict__ A, const float* __restrict__ B,
    const float* __restrict__ bias, OutT* __restrict__ C,
    const float* __restrict__ al, const float* __restrict__ ar,
    int M, int NCol, int K)
{
    // fragment smem: As[kstep(2)][mtile(8)][lane(32)][reg(4)] (half2-packed)
    //                Bs[kstep(2)][ntile(8)][lane(32)][reg(2)]
    __shared__ uint32_t As2[2 * 8 * 32 * 4];   // 8 KB
    __shared__ uint32_t Bs2[2 * 8 * 32 * 2];   // 4 KB
    __shared__ float s_el[128], s_er[128];
    const int tid = threadIdx.x;
    const int lane = tid & 31, wid = tid >> 5;
    const int wm = wid & 3, wn = wid >> 2;
    const int m0 = blockIdx.y * 128, n0 = blockIdx.x * 64;

    float acc[2][4][4];
#pragma unroll
    for (int im = 0; im < 2; im++)
#pragma unroll
        for (int in = 0; in < 4; in++)
#pragma unroll
            for (int q = 0; q < 4; q++) acc[im][in][q] = 0.f;

    float4 rA[4], rB[2];

    // prefetch slab 0
#pragma unroll
    for (int i = 0; i < 4; i++) {
        int idx = tid + 256 * i;
        int row = idx >> 3, c0 = (idx & 7) << 2;
        int gr = m0 + row;
        rA[i] = (gr < M) ? *(const float4*)(A + (size_t)gr * K + c0)
                         : make_float4(0.f, 0.f, 0.f, 0.f);
    }
#pragma unroll
    for (int i = 0; i < 2; i++) {
        int idx = tid + 256 * i;
        int row = idx >> 3, c0 = (idx & 7) << 2;
        rB[i] = *(const float4*)(B + (size_t)(n0 + row) * K + c0);
    }

    for (int kt = 0; kt < K; kt += 32) {
        __syncthreads();
        // ---- store A fragments (fp16-packed) ----
#pragma unroll
        for (int i = 0; i < 4; i++) {
            int idx = tid + 256 * i;
            int row = idx >> 3, c0 = (idx & 7) << 2;
            int ks = c0 >> 4, ck = c0 & 15;
            int q0 = ck >> 3, tig0 = (ck & 7) >> 1;
            int mt = row >> 4, rr = row & 15;
            int q1 = rr >> 3, gid = rr & 7;
            int reg = (q1 + 2 * q0) ^ (ks << 1);
            int sb = ((ks * 8 + mt) * 32 + gid * 4);
            As2[(sb + tig0) * 4 + reg]     = pk(rA[i].x, rA[i].y);
            As2[(sb + tig0 + 1) * 4 + reg] = pk(rA[i].z, rA[i].w);
        }
        // ---- store B fragments ----
#pragma unroll
        for (int i = 0; i < 2; i++) {
            int idx = tid + 256 * i;
            int row = idx >> 3, c0 = (idx & 7) << 2;
            int ks = c0 >> 4, ck = c0 & 15;
            int q0 = ck >> 3, tig0 = (ck & 7) >> 1;
            int nt = row >> 3, gid = row & 7;
            int l0 = gid * 4 + tig0;
            int base = (ks * 8 + nt) * 32;
            Bs2[(base + ((l0 + ks * 2) & 31)) * 2 + q0]     = pk(rB[i].x, rB[i].y);
            Bs2[(base + ((l0 + 1 + ks * 2) & 31)) * 2 + q0] = pk(rB[i].z, rB[i].w);
        }
        __syncthreads();

        // ---- prefetch next slab (overlaps with mma below) ----
        if (kt + 32 < K) {
#pragma unroll
            for (int i = 0; i < 4; i++) {
                int idx = tid + 256 * i;
                int row = idx >> 3, c0 = (idx & 7) << 2;
                int gr = m0 + row;
                rA[i] = (gr < M) ? *(const float4*)(A + (size_t)gr * K + kt + 32 + c0)
                                 : make_float4(0.f, 0.f, 0.f, 0.f);
            }
#pragma unroll
            for (int i = 0; i < 2; i++) {
                int idx = tid + 256 * i;
                int row = idx >> 3, c0 = (idx & 7) << 2;
                rB[i] = *(const float4*)(B + (size_t)(n0 + row) * K + kt + 32 + c0);
            }
        }

        // ---- compute: 2 ksteps x 8 mma (m16n8k16) per warp ----
#pragma unroll
        for (int ks = 0; ks < 2; ks++) {
            uint32_t a[2][4];
#pragma unroll
            for (int im = 0; im < 2; im++) {
                uint4 v = *(const uint4*)(As2 + ((ks * 8 + wm * 2 + im) * 32 + lane) * 4);
                uint32_t vc[4] = {v.x, v.y, v.z, v.w};
#pragma unroll
                for (int j = 0; j < 4; j++) a[im][j] = vc[j ^ (ks << 1)];
            }
            uint32_t b[4][2];
#pragma unroll
            for (int in = 0; in < 4; in++) {
                uint2 u = *(const uint2*)(Bs2 + ((ks * 8 + wn * 4 + in) * 32 + ((lane + ks * 2) & 31)) * 2);
                b[in][0] = u.x; b[in][1] = u.y;
            }
#pragma unroll
            for (int im = 0; im < 2; im++)
#pragma unroll
                for (int in = 0; in < 4; in++)
                    asm volatile(
                        "mma.sync.aligned.m16n8k16.row.col.f32.f16.f16.f32 "
                        "{%0,%1,%2,%3},{%4,%5,%6,%7},{%8,%9},{%0,%1,%2,%3};"
                        : "+f"(acc[im][in][0]), "+f"(acc[im][in][1]),
                          "+f"(acc[im][in][2]), "+f"(acc[im][in][3])
                        : "r"(a[im][0]), "r"(a[im][1]), "r"(a[im][2]), "r"(a[im][3]),
                          "r"(b[in][0]), "r"(b[in][1]));
        }
    }

    // ---- epilogue: store C ----
    int gid = lane >> 2, tig = lane & 3;
#pragma unroll
    for (int im = 0; im < 2; im++) {
        int r = m0 + wm * 32 + im * 16 + gid;
#pragma unroll
        for (int in = 0; in < 4; in++) {
            int c = n0 + wn * 32 + in * 8 + tig * 2;
            float b0v = bias ? bias[c] : 0.f;
            float b1v = bias ? bias[c + 1] : 0.f;
            if (r < M) {
                store_c(C, (size_t)r * NCol + c,     acc[im][in][0] + b0v);
                store_c(C, (size_t)r * NCol + c + 1, acc[im][in][1] + b1v);
            }
            if (r + 8 < M) {
                store_c(C, (size_t)(r + 8) * NCol + c,     acc[im][in][2] + b0v);
                store_c(C, (size_t)(r + 8) * NCol + c + 1, acc[im][in][3] + b1v);
            }
        }
    }

    // ---- fused el/er: this block's 64 cols == head (blockIdx.x) ----
    if (al != nullptr) {
        int head = blockIdx.x;
        const float* alh = al + head * FF;
        const float* arh = ar + head * FF;
        float sl[2][2] = {}, sr[2][2] = {};
#pragma unroll
        for (int im = 0; im < 2; im++)
#pragma unroll
            for (int in = 0; in < 4; in++) {
                int cc0 = wn * 32 + in * 8 + tig * 2;
                float a0 = alh[cc0], a1 = alh[cc0 + 1];
                float r0 = arh[cc0], r1 = arh[cc0 + 1];
                sl[im][0] += acc[im][in][0] * a0 + acc[im][in][1] * a1;
                sl[im][1] += acc[im][in][2] * a0 + acc[im][in][3] * a1;
                sr[im][0] += acc[im][in][0] * r0 + acc[im][in][1] * r1;
                sr[im][1] += acc[im][in][2] * r0 + acc[im][in][3] * r1;
            }
#pragma unroll
        for (int o = 1; o <= 2; o <<= 1)
#pragma unroll
            for (int im = 0; im < 2; im++)
#pragma unroll
                for (int hq = 0; hq < 2; hq++) {
                    sl[im][hq] += __shfl_xor_sync(0xffffffffu, sl[im][hq], o);
                    sr[im][hq] += __shfl_xor_sync(0xffffffffu, sr[im][hq], o);
                }
        __syncthreads();
        if (wn == 0 && tig == 0) {
#pragma unroll
            for (int im = 0; im < 2; im++) {
                int rl = wm * 32 + im * 16 + gid;
                s_el[rl] = sl[im][0];     s_er[rl] = sr[im][0];
                s_el[rl + 8] = sl[im][1]; s_er[rl + 8] = sr[im][1];
            }
        }
        __syncthreads();
        if (wn == 1 && tig == 0) {
#pragma unroll
            for (int im = 0; im < 2; im++) {
                int rl = wm * 32 + im * 16 + gid;
                int r = m0 + rl;
                if (r < M) {
                    g_el[r * HH + head] = s_el[rl] + sl[im][0];
                    g_er[r * HH + head] = s_er[rl] + sr[im][0];
                }
                if (r + 8 < M) {
                    g_el[(r + 8) * HH + head] = s_el[rl + 8] + sl[im][1];
                    g_er[(r + 8) * HH + head] = s_er[rl + 8] + sr[im][1];
                }
            }
        }
    }
}

// ---------------- aggregate: block per dst, warp per head ------------------
// sub = lane>>3 handles edge i*4+sub; j = lane&7 owns 8 feats (one uint4).
// p computed inline, redundantly on all 8 lanes of a sub (el load is a
// broadcast; expf is cheap MUFU) — no shfl, no edge-weight round trip.
__global__ __launch_bounds__(256) void k_agg(const float* __restrict__ bias, float* __restrict__ y) {
    int n = blockIdx.x;
    int tid = threadIdx.x, w = tid >> 5, lane = tid & 31;
    int sub = lane >> 3, j = lane & 7;
    __shared__ float s_acc[HH][FF];
    int beg = g_rowptr[n], end = g_rowptr[n + 1];
    int deg = end - beg;
    float erw = __ldg(&g_er[n * HH + w]);

    float acc[8] = {};
    float ssum = 0.f;
    int niter = (deg + 3) >> 2;
#pragma unroll 2
    for (int i = 0; i < niter; i++) {
        int ei = beg + i * 4 + sub;
        bool valid = ei < end;
        int eic = valid ? ei : beg;
        int s = __ldg(&g_col[eic]);
        float e = __ldg(&g_el[s * HH + w]) + erw;
        e = e > 0.f ? e : 0.2f * e;
        float p = valid ? __expf(e) : 0.f;
        uint4 v = *(const uint4*)(g_feat + (size_t)s * CC + w * FF + j * 8);
        float2 f0 = __half22float2(*(const __half2*)&v.x);
        float2 f1 = __half22float2(*(const __half2*)&v.y);
        float2 f2 = __half22float2(*(const __half2*)&v.z);
        float2 f3 = __half22float2(*(const __half2*)&v.w);
        acc[0] += p * f0.x; acc[1] += p * f0.y;
        acc[2] += p * f1.x; acc[3] += p * f1.y;
        acc[4] += p * f2.x; acc[5] += p * f2.y;
        acc[6] += p * f3.x; acc[7] += p * f3.y;
        ssum += p;
    }
    // reduce the 4 edge-subgroups (lane bits 3,4)
#pragma unroll
    for (int o = 8; o <= 16; o <<= 1) {
        ssum += __shfl_xor_sync(0xffffffffu, ssum, o);
#pragma unroll
        for (int k = 0; k < 8; k++) acc[k] += __shfl_xor_sync(0xffffffffu, acc[k], o);
    }
    float inv = (deg > 0) ? 1.0f / ssum : 0.f;
    if (sub == 0) {
#pragma unroll
        for (int k = 0; k < 8; k++)
            s_acc[w][j * 8 + k] = acc[k] * inv + bias[w * FF + j * 8 + k];
    }
    __syncthreads();

    // sum heads + leaky(0.01)
    if (tid < FF) {
        float v = 0.f;
#pragma unroll
        for (int hh = 0; hh < HH; hh++) v += s_acc[hh][tid];
        v = v > 0.f ? v : 0.01f * v;
        y[(size_t)n * FF + tid] = v;
    }
}

// ---------------- launcher -------------------------------------------------
extern "C" void kernel_launch(void* const* d_in, const int* in_sizes, int n_in,
                              void* d_out, int out_size) {
    const float* x   = (const float*)d_in[0];
    const int*   src = (const int*)d_in[1];
    const int*   dst = (const int*)d_in[2];
    const float* W1  = (const float*)d_in[3];
    const float* al1 = (const float*)d_in[4];
    const float* ar1 = (const float*)d_in[5];
    const float* b1  = (const float*)d_in[6];
    const float* W2  = (const float*)d_in[7];
    const float* al2 = (const float*)d_in[8];
    const float* ar2 = (const float*)d_in[9];
    const float* b2  = (const float*)d_in[10];
    const float* W3  = (const float*)d_in[11];
    const float* al3 = (const float*)d_in[12];
    const float* ar3 = (const float*)d_in[13];
    const float* b3  = (const float*)d_in[14];
    const float* Wm  = (const float*)d_in[15];
    const float* bm  = (const float*)d_in[16];
    float* out = (float*)d_out;

    __half* feat_p;
    float* h_p;
    cudaGetSymbolAddress((void**)&feat_p, g_feat);
    cudaGetSymbolAddress((void**)&h_p, g_h);

    // CSR by dst (rebuilt every call; identical work each time)
    k_zero<<<(NN + 255) / 256, 256>>>();
    k_hist<<<(EE + 255) / 256, 256>>>(dst);
    k_scan<<<1, 1024>>>();
    k_scatter<<<(EE + 255) / 256, 256>>>(src, dst);

    dim3 gproj(CC / 64, (NN + 127) / 128);

    // layer 1 (K=128)
    k_gemm_tc<__half><<<gproj, 256>>>(x, W1, nullptr, feat_p, al1, ar1, NN, CC, 128);
    k_agg<<<NN, 256>>>(b1, h_p);

    // layer 2 (K=64)
    k_gemm_tc<__half><<<gproj, 256>>>(h_p, W2, nullptr, feat_p, al2, ar2, NN, CC, 64);
    k_agg<<<NN, 256>>>(b2, h_p);

    // layer 3 (K=64)
    k_gemm_tc<__half><<<gproj, 256>>>(h_p, W3, nullptr, feat_p, al3, ar3, NN, CC, 64);
    k_agg<<<NN, 256>>>(b3, h_p);

    // final linear: out = h @ Wm^T + bm  [N,OUT]
    k_gemm_tc<float><<<dim3(1, (NN + 127) / 128), 256>>>(h_p, Wm, bm, out,
                                                         nullptr, nullptr, NN, FF, FF);
}